// round 7
// baseline (speedup 1.0000x reference)
#include <cuda_runtime.h>
#include <math.h>

#define NE    14
#define NSV   256
#define NPVs  33
#define NPAIR 196
#define NORB  112
#define NFB   3

struct __align__(16) Smem {
    float2 svp[NE * NSV];        // 28672 B, packed (el0, el1)
    float  pv[2][NPAIR * NPVs];  // 51744 B; reused as packed orbm after last layer
    float2 scrP[896];            // 7168 B, ext means packed: [dn*448 + e*32 + k]
    float2 mumdP[512];           // 4096 B, packed mu|md
    float2 cmP[256];             // 2048 B, packed bias
    float2 cred[4][256];         // 8192 B, cm k-split partials; aliased as pin in phase0
    float  scr0[2][112];         // 896 B, layer0 pu0/pd0
    float2 m0P[16];              // 128 B, layer0 mu0|md0 packed
    float  sin8[2][NE][8];       // 896 B
    float  env[2][NE];           // 112 B
    float  rl[2][NE][3];         // 336 B
    float  ldet[2][32];          // 256 B
    float  sgn[2][32];           // 256 B
};                               // total ~104.8 KB -> 2 CTAs/SM

union U64 { unsigned long long u; float2 f; };

__device__ __forceinline__ void ffma2(unsigned long long &d, unsigned long long a, unsigned long long b) {
    asm("fma.rn.f32x2 %0, %1, %2, %0;" : "+l"(d) : "l"(a), "l"(b));
}
__device__ __forceinline__ unsigned long long dup2(float x) {
    unsigned long long r;
    asm("mov.b64 %0, {%1, %1};" : "=l"(r) : "f"(x));
    return r;
}
__device__ __forceinline__ float fast_tanh(float x) {
    float e = __expf(2.0f * x);
    return 1.0f - __fdividef(2.0f, e + 1.0f);
}

__global__ void __launch_bounds__(256, 2)
ansatz_kernel(const float* __restrict__ r,
              const float* __restrict__ s_w0, const float* __restrict__ s_b0,
              const float* __restrict__ s_w,  const float* __restrict__ s_b,
              const float* __restrict__ p_w0, const float* __restrict__ p_b0,
              const float* __restrict__ p_w,  const float* __restrict__ p_b,
              const float* __restrict__ va_w, const float* __restrict__ va_b,
              const float* __restrict__ wu_w, const float* __restrict__ wu_b,
              const float* __restrict__ wd_w, const float* __restrict__ wd_b,
              const float* __restrict__ wf_w,
              float* __restrict__ out, int nb)
{
    extern __shared__ char smem_raw[];
    Smem& s = *reinterpret_cast<Smem*>(smem_raw);

    const int t    = threadIdx.x;
    const int lane = t & 31;
    const int wid  = t >> 5;          // 0..7
    const int b0   = blockIdx.x * 2;
    const float inv7 = 1.0f / 7.0f;
    const int tc   = t;               // column for 256-wide phases

    float* pinA = (float*)s.cred;     // layer0 pair inputs alias (6272 B <= 8192 B)

    // ---------------- Phase 0: geometry ----------------
    for (int q = t; q < 2 * NE * 3; q += 256) {
        int el = q / (NE * 3);
        int bel = b0 + el; if (bel >= nb) bel = nb - 1;
        ((float*)s.rl[el])[q - el * (NE * 3)] = r[bel * (NE * 3) + (q - el * (NE * 3))];
    }
    __syncthreads();

    if (t < 2 * NE) {
        int el = t / NE, e = t - el * NE;
        float x = s.rl[el][e][0], y = s.rl[el][e][1], z = s.rl[el][e][2];
        float ev = 0.f;
        #pragma unroll
        for (int a = 0; a < 2; ++a) {
            float dz = z - (a ? 1.4f : 0.0f);
            float len = sqrtf(x * x + y * y + dz * dz);
            s.sin8[el][e][a * 4 + 0] = x;
            s.sin8[el][e][a * 4 + 1] = y;
            s.sin8[el][e][a * 4 + 2] = dz;
            s.sin8[el][e][a * 4 + 3] = len;
            ev += __expf(-len);
        }
        s.env[el][e] = ev;
    }
    for (int idx = t; idx < 2 * NPAIR; idx += 256) {
        int el = idx / NPAIR, pr = idx - el * NPAIR;
        int i = pr / 14, j = pr - i * 14;
        float dx = s.rl[el][j][0] - s.rl[el][i][0];
        float dy = s.rl[el][j][1] - s.rl[el][i][1];
        float dz = s.rl[el][j][2] - s.rl[el][i][2];
        float ax = dx, ay = dy, az = dz;
        if (i == j) { ax += 1.f; ay += 1.f; az += 1.f; }
        float len = sqrtf(ax * ax + ay * ay + az * az);
        pinA[idx * 4 + 0] = dx; pinA[idx * 4 + 1] = dy;
        pinA[idx * 4 + 2] = dz; pinA[idx * 4 + 3] = len;
    }
    __syncthreads();

    // layer-0 means
    if (t < 32) {
        int el = t >> 4, q = t & 15;
        int k = q & 7, half = q >> 3;
        float su = 0.f;
        #pragma unroll
        for (int e = 0; e < 7; ++e) su += s.sin8[el][half * 7 + e][k];
        ((float*)&s.m0P[half * 8 + k])[el] = su * inv7;
    }
    if (t < 224) {
        int el = t / 112, q = t - el * 112;
        int dn = (q >= 56) ? 1 : 0;
        int qq = q - dn * 56;
        int e = qq >> 2, k = qq & 3;
        int i0 = dn ? 7 : 0;
        float su = 0.f;
        #pragma unroll
        for (int ii = 0; ii < 7; ++ii) su += pinA[(el * 196 + (i0 + ii) * 14 + e) * 4 + k];
        s.scr0[el][q] = su * inv7;
    }
    __syncthreads();

    // ---------------- Layer 0 ----------------
    {
        // pair stream: 392 rows over 256 threads
        for (int it = t; it < 2 * NPAIR; it += 256) {
            int el = it / NPAIR, pr = it - el * NPAIR;
            const float* pin = pinA + it * 4;
            float r0 = pin[0], r1 = pin[1], r2 = pin[2], r3 = pin[3];
            #pragma unroll
            for (int c2 = 0; c2 < 32; ++c2) {
                float v = p_b0[c2]
                        + r0 * p_w0[0 * 32 + c2] + r1 * p_w0[1 * 32 + c2]
                        + r2 * p_w0[2 * 32 + c2] + r3 * p_w0[3 * 32 + c2];
                s.pv[el][pr * NPVs + c2] = fast_tanh(v);
            }
        }
        // electron stream: column tc, both elements
        float c00 = s_b0[tc], c01 = s_b0[tc];
        #pragma unroll
        for (int k = 0; k < 8; ++k) {
            float wA = s_w0[(8 + k) * 256 + tc];
            float wB = s_w0[(16 + k) * 256 + tc];
            float2 m = s.m0P[k], n = s.m0P[8 + k];
            c00 += m.x * wA + n.x * wB;
            c01 += m.y * wA + n.y * wB;
        }
        float acc0[NE], acc1[NE];
        #pragma unroll
        for (int e = 0; e < NE; ++e) { acc0[e] = c00; acc1[e] = c01; }
        #pragma unroll
        for (int k = 0; k < 8; ++k) {
            float w = s_w0[k * 256 + tc];
            #pragma unroll
            for (int e = 0; e < NE; ++e) {
                acc0[e] += s.sin8[0][e][k] * w;
                acc1[e] += s.sin8[1][e][k] * w;
            }
        }
        #pragma unroll
        for (int k = 0; k < 4; ++k) {
            float wu = s_w0[(24 + k) * 256 + tc];
            float wd = s_w0[(28 + k) * 256 + tc];
            #pragma unroll
            for (int e = 0; e < NE; ++e) {
                acc0[e] += s.scr0[0][e * 4 + k] * wu + s.scr0[0][56 + e * 4 + k] * wd;
                acc1[e] += s.scr0[1][e * 4 + k] * wu + s.scr0[1][56 + e * 4 + k] * wd;
            }
        }
        #pragma unroll
        for (int e = 0; e < NE; ++e)
            s.svp[e * NSV + tc] = make_float2(fast_tanh(acc0[e]), fast_tanh(acc1[e]));
    }
    __syncthreads();

    // ---------------- FB layers + final va ----------------
    for (int il = 0; il <= NFB; ++il) {
        const bool last = (il == NFB);
        const float* WL = last ? va_w : (s_w + il * (832 * 256));
        const float* bL = last ? va_b : (s_b + il * 256);
        const float* PW = p_w + il * (32 * 32);
        const float* Pb = p_b + il * 32;

        // (a) means (packed) + cm bias init + ext means packed
        {
            float2 su = make_float2(0.f, 0.f), sd = make_float2(0.f, 0.f);
            #pragma unroll
            for (int e = 0; e < 7; ++e) {
                float2 a = s.svp[e * NSV + tc];       su.x += a.x; su.y += a.y;
                float2 b = s.svp[(7 + e) * NSV + tc]; sd.x += b.x; sd.y += b.y;
            }
            s.mumdP[tc]       = make_float2(su.x * inv7, su.y * inv7);
            s.mumdP[256 + tc] = make_float2(sd.x * inv7, sd.y * inv7);
            float bv = bL[tc];
            s.cmP[tc] = make_float2(bv, bv);
        }
        for (int idx = t; idx < 896; idx += 256) {
            int dn = idx / 448, q = idx - dn * 448;
            int e = q >> 5, k = q & 31;
            int i0 = dn * 7;
            float s0 = 0.f, s1 = 0.f;
            #pragma unroll
            for (int ii = 0; ii < 7; ++ii) {
                int off = ((i0 + ii) * 14 + e) * NPVs + k;
                s0 += s.pv[0][off];
                s1 += s.pv[1][off];
            }
            s.scrP[idx] = make_float2(s0 * inv7, s1 * inv7);
        }
        __syncthreads();

        // (b) pair GEMM: 392 rows over 256 threads
        if (!last) {
            for (int it = t; it < 2 * NPAIR; it += 256) {
                int el = it / NPAIR, pr = it - el * NPAIR;
                float row[32];
                #pragma unroll
                for (int k = 0; k < 32; ++k) row[k] = s.pv[el][pr * NPVs + k];
                unsigned long long o[16];
                const ulonglong2* pb2 = (const ulonglong2*)Pb;
                #pragma unroll
                for (int q = 0; q < 8; ++q) {
                    ulonglong2 bv = pb2[q];
                    o[2 * q] = bv.x; o[2 * q + 1] = bv.y;
                }
                #pragma unroll
                for (int k = 0; k < 32; ++k) {
                    unsigned long long rk = dup2(row[k]);
                    const ulonglong2* w2 = (const ulonglong2*)(PW + k * 32);
                    #pragma unroll
                    for (int q = 0; q < 8; ++q) {
                        ulonglong2 wv = w2[q];
                        ffma2(o[2 * q], rk, wv.x);
                        ffma2(o[2 * q + 1], rk, wv.y);
                    }
                }
                #pragma unroll
                for (int q = 0; q < 16; ++q) {
                    U64 u; u.u = o[q];
                    s.pv[el][pr * NPVs + 2 * q]     = fast_tanh(u.f.x) + row[2 * q];
                    s.pv[el][pr * NPVs + 2 * q + 1] = fast_tanh(u.f.y) + row[2 * q + 1];
                }
            }
        }

        // (c) cm rank-1 partials: warps 0-3, 128 k each, packed accumulators
        if (wid < 4) {
            const int kb = wid * 128;
            const int c0m = lane * 8;
            unsigned long long ca[8];
            #pragma unroll
            for (int j = 0; j < 8; ++j) ca[j] = 0ull;
            for (int k = kb; k < kb + 128; ++k) {
                const float* wp = WL + (256 + k) * 256 + c0m;
                float4 wa = *(const float4*)wp;
                float4 wb = *(const float4*)(wp + 4);
                unsigned long long m2 = *(const unsigned long long*)&s.mumdP[k];
                ffma2(ca[0], m2, dup2(wa.x)); ffma2(ca[1], m2, dup2(wa.y));
                ffma2(ca[2], m2, dup2(wa.z)); ffma2(ca[3], m2, dup2(wa.w));
                ffma2(ca[4], m2, dup2(wb.x)); ffma2(ca[5], m2, dup2(wb.y));
                ffma2(ca[6], m2, dup2(wb.z)); ffma2(ca[7], m2, dup2(wb.w));
            }
            #pragma unroll
            for (int j = 0; j < 8; ++j) { U64 u; u.u = ca[j]; s.cred[wid][c0m + j] = u.f; }
        }

        // (d) main electron GEMM: 8 warps = eh(2) x ch(4), lane = 2 cols, full K, packed
        const int eh = wid >> 2;
        const int ch = wid & 3;
        const int e0 = eh * 7;
        const int c0 = ch * 64 + lane * 2;
        unsigned long long acc[7][2];
        #pragma unroll
        for (int i = 0; i < 7; ++i) { acc[i][0] = 0ull; acc[i][1] = 0ull; }

        #pragma unroll 2
        for (int kk = 0; kk < 256; kk += 4) {
            const float* wp = WL + kk * 256 + c0;
            float2 wr0 = *(const float2*)(wp);
            float2 wr1 = *(const float2*)(wp + 256);
            float2 wr2 = *(const float2*)(wp + 512);
            float2 wr3 = *(const float2*)(wp + 768);
            unsigned long long w00 = dup2(wr0.x), w01 = dup2(wr0.y);
            unsigned long long w10 = dup2(wr1.x), w11 = dup2(wr1.y);
            unsigned long long w20 = dup2(wr2.x), w21 = dup2(wr2.y);
            unsigned long long w30 = dup2(wr3.x), w31 = dup2(wr3.y);
            #pragma unroll
            for (int i = 0; i < 7; ++i) {
                ulonglong2 A = *(const ulonglong2*)&s.svp[(e0 + i) * NSV + kk];
                ulonglong2 B = *(const ulonglong2*)&s.svp[(e0 + i) * NSV + kk + 2];
                ffma2(acc[i][0], A.x, w00); ffma2(acc[i][1], A.x, w01);
                ffma2(acc[i][0], A.y, w10); ffma2(acc[i][1], A.y, w11);
                ffma2(acc[i][0], B.x, w20); ffma2(acc[i][1], B.x, w21);
                ffma2(acc[i][0], B.y, w30); ffma2(acc[i][1], B.y, w31);
            }
        }
        // ext rows (pu 768..799 with scrP[0], pd 800..831 with scrP[1])
        #pragma unroll
        for (int blk = 0; blk < 2; ++blk) {
            #pragma unroll 2
            for (int kk = 0; kk < 32; kk += 4) {
                const float* wp = WL + (768 + blk * 32 + kk) * 256 + c0;
                float2 wr0 = *(const float2*)(wp);
                float2 wr1 = *(const float2*)(wp + 256);
                float2 wr2 = *(const float2*)(wp + 512);
                float2 wr3 = *(const float2*)(wp + 768);
                unsigned long long w00 = dup2(wr0.x), w01 = dup2(wr0.y);
                unsigned long long w10 = dup2(wr1.x), w11 = dup2(wr1.y);
                unsigned long long w20 = dup2(wr2.x), w21 = dup2(wr2.y);
                unsigned long long w30 = dup2(wr3.x), w31 = dup2(wr3.y);
                #pragma unroll
                for (int i = 0; i < 7; ++i) {
                    const float2* sp = &s.scrP[blk * 448 + (e0 + i) * 32 + kk];
                    ulonglong2 A = *(const ulonglong2*)(sp);
                    ulonglong2 B = *(const ulonglong2*)(sp + 2);
                    ffma2(acc[i][0], A.x, w00); ffma2(acc[i][1], A.x, w01);
                    ffma2(acc[i][0], A.y, w10); ffma2(acc[i][1], A.y, w11);
                    ffma2(acc[i][0], B.x, w20); ffma2(acc[i][1], B.x, w21);
                    ffma2(acc[i][0], B.y, w30); ffma2(acc[i][1], B.y, w31);
                }
            }
        }
        __syncthreads();   // cred complete; all svp reads done

        // (e) fused epilogue (warp owns its tile)
        {
            float2 cv0 = s.cmP[c0], cv1 = s.cmP[c0 + 1];
            #pragma unroll
            for (int ss = 0; ss < 4; ++ss) {
                float2 a = s.cred[ss][c0], b = s.cred[ss][c0 + 1];
                cv0.x += a.x; cv0.y += a.y; cv1.x += b.x; cv1.y += b.y;
            }
            #pragma unroll
            for (int i = 0; i < 7; ++i) {
                U64 u0; u0.u = acc[i][0];
                U64 u1; u1.u = acc[i][1];
                float2 o0, o1;
                o0.x = fast_tanh(u0.f.x + cv0.x); o0.y = fast_tanh(u0.f.y + cv0.y);
                o1.x = fast_tanh(u1.f.x + cv1.x); o1.y = fast_tanh(u1.f.y + cv1.y);
                if (!last) {
                    float2 r0 = s.svp[(e0 + i) * NSV + c0];
                    float2 r1 = s.svp[(e0 + i) * NSV + c0 + 1];
                    o0.x += r0.x; o0.y += r0.y;
                    o1.x += r1.x; o1.y += r1.y;
                }
                s.svp[(e0 + i) * NSV + c0]     = o0;
                s.svp[(e0 + i) * NSV + c0 + 1] = o1;
            }
        }
        __syncthreads();
    }

    // ---------------- Orbitals (packed into pv region) ----------------
    float* orbmF = (float*)s.pv;   // [ (e*112 + o)*2 + el ]
    for (int idx = t; idx < NE * NORB; idx += 256) {
        int e = idx / NORB, o = idx - e * NORB;
        float bv = (e < 7) ? wu_b[o] : wd_b[o];
        orbmF[idx * 2 + 0] = bv;
        orbmF[idx * 2 + 1] = bv;
    }
    __syncthreads();
    {
        const int kh  = wid & 3;
        const int eh2 = wid >> 2;
        const int e0o = eh2 * 7;
        const int oc0 = lane * 4;
        if (oc0 < NORB) {
            const float* W = eh2 ? wd_w : wu_w;
            unsigned long long oa[7][4];
            #pragma unroll
            for (int i = 0; i < 7; ++i)
                #pragma unroll
                for (int p = 0; p < 4; ++p) oa[i][p] = 0ull;
            const int kb = kh * 64;
            for (int kk = 0; kk < 64; kk += 4) {
                const int k = kb + kk;
                float4 w0 = *(const float4*)(W + (k + 0) * NORB + oc0);
                float4 w1 = *(const float4*)(W + (k + 1) * NORB + oc0);
                float4 w2 = *(const float4*)(W + (k + 2) * NORB + oc0);
                float4 w3 = *(const float4*)(W + (k + 3) * NORB + oc0);
                unsigned long long d00 = dup2(w0.x), d01 = dup2(w0.y), d02 = dup2(w0.z), d03 = dup2(w0.w);
                unsigned long long d10 = dup2(w1.x), d11 = dup2(w1.y), d12 = dup2(w1.z), d13 = dup2(w1.w);
                unsigned long long d20 = dup2(w2.x), d21 = dup2(w2.y), d22 = dup2(w2.z), d23 = dup2(w2.w);
                unsigned long long d30 = dup2(w3.x), d31 = dup2(w3.y), d32 = dup2(w3.z), d33 = dup2(w3.w);
                #pragma unroll
                for (int i = 0; i < 7; ++i) {
                    ulonglong2 A = *(const ulonglong2*)&s.svp[(e0o + i) * NSV + k];
                    ulonglong2 B = *(const ulonglong2*)&s.svp[(e0o + i) * NSV + k + 2];
                    ffma2(oa[i][0], A.x, d00); ffma2(oa[i][1], A.x, d01);
                    ffma2(oa[i][2], A.x, d02); ffma2(oa[i][3], A.x, d03);
                    ffma2(oa[i][0], A.y, d10); ffma2(oa[i][1], A.y, d11);
                    ffma2(oa[i][2], A.y, d12); ffma2(oa[i][3], A.y, d13);
                    ffma2(oa[i][0], B.x, d20); ffma2(oa[i][1], B.x, d21);
                    ffma2(oa[i][2], B.x, d22); ffma2(oa[i][3], B.x, d23);
                    ffma2(oa[i][0], B.y, d30); ffma2(oa[i][1], B.y, d31);
                    ffma2(oa[i][2], B.y, d32); ffma2(oa[i][3], B.y, d33);
                }
            }
            #pragma unroll
            for (int i = 0; i < 7; ++i)
                #pragma unroll
                for (int p = 0; p < 4; ++p) {
                    U64 u; u.u = oa[i][p];
                    int base = ((e0o + i) * NORB + oc0 + p) * 2;
                    atomicAdd(&orbmF[base + 0], u.f.x);
                    atomicAdd(&orbmF[base + 1], u.f.y);
                }
        }
    }
    __syncthreads();
    for (int idx = t; idx < NE * NORB; idx += 256) {
        int e = idx / NORB;
        float2 v = *(float2*)&orbmF[idx * 2];
        v.x *= s.env[0][e];
        v.y *= s.env[1][e];
        *(float2*)&orbmF[idx * 2] = v;
    }
    __syncthreads();

    // ---------------- 2 x 32 slogdets of 7x7 ----------------
    if (t < 64) {
        const int el = t >> 5, tt = t & 31;
        const int sp = tt >> 4, d = tt & 15;
        float m[7][7];
        #pragma unroll
        for (int j = 0; j < 7; ++j) {
            #pragma unroll
            for (int i = 0; i < 7; ++i)
                m[j][i] = orbmF[((sp * 7 + i) * NORB + j * 16 + d) * 2 + el];
        }
        float ld = 0.f, sg = 1.f;
        #pragma unroll
        for (int col = 0; col < 7; ++col) {
            #pragma unroll
            for (int rr = col + 1; rr < 7; ++rr) {
                if (fabsf(m[rr][col]) > fabsf(m[col][col])) {
                    sg = -sg;
                    #pragma unroll
                    for (int cc = 0; cc < 7; ++cc) {
                        float tmp = m[col][cc]; m[col][cc] = m[rr][cc]; m[rr][cc] = tmp;
                    }
                }
            }
            float piv = m[col][col];
            sg = (piv < 0.f) ? -sg : sg;
            ld += __logf(fabsf(piv));
            float inv = 1.f / piv;
            #pragma unroll
            for (int rr = col + 1; rr < 7; ++rr) {
                float f = m[rr][col] * inv;
                #pragma unroll
                for (int cc = col + 1; cc < 7; ++cc)
                    m[rr][cc] -= f * m[col][cc];
            }
        }
        s.ldet[el][tt] = ld;
        s.sgn[el][tt] = sg;
    }
    __syncthreads();

    if (t < 2 && (b0 + t) < nb) {
        const int el = t;
        float l[16], mx = -3.4e38f;
        #pragma unroll
        for (int d = 0; d < 16; ++d) {
            l[d] = s.ldet[el][d] + s.ldet[el][16 + d];
            mx = fmaxf(mx, l[d]);
        }
        float psi = 0.f;
        #pragma unroll
        for (int d = 0; d < 16; ++d)
            psi += s.sgn[el][d] * s.sgn[el][16 + d] * __expf(l[d] - mx) * wf_w[d];
        out[b0 + el] = __logf(fabsf(psi)) + mx;
    }
}

extern "C" void kernel_launch(void* const* d_in, const int* in_sizes, int n_in,
                              void* d_out, int out_size)
{
    const float* r    = (const float*)d_in[0];
    const float* s_w0 = (const float*)d_in[1];
    const float* s_b0 = (const float*)d_in[2];
    const float* s_w  = (const float*)d_in[3];
    const float* s_b  = (const float*)d_in[4];
    const float* p_w0 = (const float*)d_in[5];
    const float* p_b0 = (const float*)d_in[6];
    const float* p_w  = (const float*)d_in[7];
    const float* p_b  = (const float*)d_in[8];
    const float* va_w = (const float*)d_in[9];
    const float* va_b = (const float*)d_in[10];
    const float* wu_w = (const float*)d_in[11];
    const float* wu_b = (const float*)d_in[12];
    const float* wd_w = (const float*)d_in[13];
    const float* wd_b = (const float*)d_in[14];
    const float* wf_w = (const float*)d_in[15];

    const int nb  = in_sizes[0] / (14 * 3);
    const int nb2 = (nb + 1) / 2;
    const int smem = (int)sizeof(Smem);
    cudaFuncSetAttribute(ansatz_kernel, cudaFuncAttributeMaxDynamicSharedMemorySize, smem);
    ansatz_kernel<<<nb2, 256, smem>>>(r, s_w0, s_b0, s_w, s_b, p_w0, p_b0, p_w, p_b,
                                      va_w, va_b, wu_w, wu_b, wd_w, wd_b, wf_w,
                                      (float*)d_out, nb);
}

// round 8
// speedup vs baseline: 2.4033x; 2.4033x over previous
#include <cuda_runtime.h>
#include <math.h>

#define NE    14
#define NSV   256
#define NPVs  33
#define NPAIR 196
#define NORB  112
#define NFB   3

struct __align__(16) Smem {
    float sv[2][NE][NSV];        // 28672 B
    float pv[2][NPAIR * NPVs];   // 51744 B (reused as orbm swizzled)
    float red[4][2][NE][NSV];    // 114688 B k-split partials (plain stores)
    float scr[2][896];
    float mumd[2][512];
    float cm[2][NSV];
    float pwS[1024];             // staged pair weights (per layer)
    float pbS[32];               // staged pair bias
    float sin8[2][NE][8];
    float env[2][NE];
    float rl[2][NE][3];
    float ldet[2][32];
    float sgn[2][32];
};

union U64 { unsigned long long u; float2 f; };

__device__ __forceinline__ void ffma2(unsigned long long &d, unsigned long long a, unsigned long long b) {
    asm("fma.rn.f32x2 %0, %1, %2, %0;" : "+l"(d) : "l"(a), "l"(b));
}
__device__ __forceinline__ unsigned long long dup2(float x) {
    unsigned long long r;
    asm("mov.b64 %0, {%1, %1};" : "=l"(r) : "f"(x));
    return r;
}
__device__ __forceinline__ int swz(int c)  { return c ^ (c >> 5); }
__device__ __forceinline__ int swzo(int o) { return o ^ (o >> 5); }

__device__ __forceinline__ float fast_tanh(float x) {
    float e = __expf(2.0f * x);
    return 1.0f - __fdividef(2.0f, e + 1.0f);
}

__global__ void __launch_bounds__(512, 1)
ansatz_kernel(const float* __restrict__ r,
              const float* __restrict__ s_w0, const float* __restrict__ s_b0,
              const float* __restrict__ s_w,  const float* __restrict__ s_b,
              const float* __restrict__ p_w0, const float* __restrict__ p_b0,
              const float* __restrict__ p_w,  const float* __restrict__ p_b,
              const float* __restrict__ va_w, const float* __restrict__ va_b,
              const float* __restrict__ wu_w, const float* __restrict__ wu_b,
              const float* __restrict__ wd_w, const float* __restrict__ wd_b,
              const float* __restrict__ wf_w,
              float* __restrict__ out, int nb)
{
    extern __shared__ char smem_raw[];
    Smem& s = *reinterpret_cast<Smem*>(smem_raw);

    const int t    = threadIdx.x;
    const int lane = t & 31;
    const int wid  = t >> 5;
    const int b0   = blockIdx.x * 2;
    const float inv7 = 1.0f / 7.0f;

    const int tel = t >> 8;
    const int tc  = t & 255;

    // ---------------- Phase 0: geometry ----------------
    for (int q = t; q < 2 * NE * 3; q += 512) {
        int el = q / (NE * 3);
        int bel = b0 + el; if (bel >= nb) bel = nb - 1;
        ((float*)s.rl[el])[q - el * (NE * 3)] = r[bel * (NE * 3) + (q - el * (NE * 3))];
    }
    __syncthreads();

    if (t < 2 * NE) {
        int el = t / NE, e = t - el * NE;
        float x = s.rl[el][e][0], y = s.rl[el][e][1], z = s.rl[el][e][2];
        float ev = 0.f;
        #pragma unroll
        for (int a = 0; a < 2; ++a) {
            float dz = z - (a ? 1.4f : 0.0f);
            float len = sqrtf(x * x + y * y + dz * dz);
            s.sin8[el][e][a * 4 + 0] = x;
            s.sin8[el][e][a * 4 + 1] = y;
            s.sin8[el][e][a * 4 + 2] = dz;
            s.sin8[el][e][a * 4 + 3] = len;
            ev += __expf(-len);
        }
        s.env[el][e] = ev;
    }
    if (t < 2 * NPAIR) {
        int el = t / NPAIR, pr = t - el * NPAIR;
        int i = pr / 14, j = pr - i * 14;
        float dx = s.rl[el][j][0] - s.rl[el][i][0];
        float dy = s.rl[el][j][1] - s.rl[el][i][1];
        float dz = s.rl[el][j][2] - s.rl[el][i][2];
        float ax = dx, ay = dy, az = dz;
        if (i == j) { ax += 1.f; ay += 1.f; az += 1.f; }
        float len = sqrtf(ax * ax + ay * ay + az * az);
        s.scr[el][pr * 4 + 0] = dx; s.scr[el][pr * 4 + 1] = dy;
        s.scr[el][pr * 4 + 2] = dz; s.scr[el][pr * 4 + 3] = len;
    }
    __syncthreads();

    // layer-0 means
    if (t < 32) {
        int el = t >> 4, q = t & 15;
        int k = q & 7, half = q >> 3;
        float su = 0.f;
        #pragma unroll
        for (int e = 0; e < 7; ++e) su += s.sin8[el][half * 7 + e][k];
        s.mumd[el][half * 8 + k] = su * inv7;
    }
    if (t >= 64 && t < 64 + 224) {
        int q2 = t - 64;
        int el = q2 / 112, q = q2 - el * 112;
        int dn = (q >= 56) ? 1 : 0;
        int qq = q - dn * 56;
        int e = qq >> 2, k = qq & 3;
        int i0 = dn ? 7 : 0;
        float su = 0.f;
        #pragma unroll
        for (int ii = 0; ii < 7; ++ii) su += s.scr[el][((i0 + ii) * 14 + e) * 4 + k];
        s.scr[el][784 + dn * 56 + e * 4 + k] = su * inv7;
    }
    __syncthreads();

    // ---------------- Layer 0 ----------------
    {
        float pnew[32];
        const bool prow = (t < 2 * NPAIR);
        int pel = 0, pr = 0;
        if (prow) {
            pel = t / NPAIR; pr = t - pel * NPAIR;
            const float* pin = s.scr[pel] + pr * 4;
            float r0 = pin[0], r1 = pin[1], r2 = pin[2], r3 = pin[3];
            #pragma unroll
            for (int c2 = 0; c2 < 32; ++c2) {
                float v = p_b0[c2]
                        + r0 * p_w0[0 * 32 + c2] + r1 * p_w0[1 * 32 + c2]
                        + r2 * p_w0[2 * 32 + c2] + r3 * p_w0[3 * 32 + c2];
                pnew[c2] = fast_tanh(v);
            }
        }
        if (t < 512) {
            float cm0 = s_b0[tc];
            #pragma unroll
            for (int k = 0; k < 8; ++k)
                cm0 += s.mumd[tel][k] * s_w0[(8 + k) * 256 + tc] + s.mumd[tel][8 + k] * s_w0[(16 + k) * 256 + tc];
            float acc[NE];
            #pragma unroll
            for (int e = 0; e < NE; ++e) acc[e] = cm0;
            #pragma unroll
            for (int k = 0; k < 8; ++k) {
                float w = s_w0[k * 256 + tc];
                #pragma unroll
                for (int e = 0; e < NE; ++e) acc[e] += s.sin8[tel][e][k] * w;
            }
            const float* pu0 = s.scr[tel] + 784;
            const float* pd0 = s.scr[tel] + 840;
            #pragma unroll
            for (int k = 0; k < 4; ++k) {
                float wuv = s_w0[(24 + k) * 256 + tc];
                float wdv = s_w0[(28 + k) * 256 + tc];
                #pragma unroll
                for (int e = 0; e < NE; ++e)
                    acc[e] += pu0[e * 4 + k] * wuv + pd0[e * 4 + k] * wdv;
            }
            #pragma unroll
            for (int e = 0; e < NE; ++e) s.sv[tel][e][tc] = fast_tanh(acc[e]);
        }
        if (prow) {
            #pragma unroll
            for (int c2 = 0; c2 < 32; ++c2) s.pv[pel][pr * NPVs + c2] = pnew[c2];
        }
    }
    __syncthreads();

    // ---------------- FB layers + final va ----------------
    for (int il = 0; il <= NFB; ++il) {
        const bool last = (il == NFB);
        const float* WL = last ? va_w : (s_w + il * (832 * 256));
        const float* bL = last ? va_b : (s_b + il * 256);
        const float* PW = p_w + il * (32 * 32);
        const float* Pb = p_b + il * 32;

        // (a) means + cm init + pair-weight staging
        {
            float su = 0.f, sd = 0.f;
            #pragma unroll
            for (int e = 0; e < 7; ++e) { su += s.sv[tel][e][tc]; sd += s.sv[tel][7 + e][tc]; }
            s.mumd[tel][tc]       = su * inv7;
            s.mumd[tel][256 + tc] = sd * inv7;
            s.cm[tel][swz(tc)]    = bL[tc];
        }
        if (!last) {
            #pragma unroll
            for (int idx = t; idx < 1024; idx += 512) s.pwS[idx] = PW[idx];
            if (t < 32) s.pbS[t] = Pb[t];
        }
        for (int idx = t; idx < 2 * 896; idx += 512) {
            int el = idx / 896, q2 = idx - el * 896;
            int dn = (q2 >= 448) ? 1 : 0;
            int q = q2 - dn * 448;
            int e = q >> 5, k = q & 31;
            int i0 = dn ? 7 : 0;
            float su = 0.f;
            #pragma unroll
            for (int ii = 0; ii < 7; ++ii) su += s.pv[el][((i0 + ii) * 14 + e) * NPVs + k];
            s.scr[el][q2] = su * inv7;
        }
        __syncthreads();

        // (b) pair GEMM — weights from shared
        if (!last && t < 2 * NPAIR) {
            int el = t / NPAIR, pr = t - el * NPAIR;
            float row[32];
            #pragma unroll
            for (int k = 0; k < 32; ++k) row[k] = s.pv[el][pr * NPVs + k];
            unsigned long long o[16];
            const ulonglong2* pb2 = (const ulonglong2*)s.pbS;
            #pragma unroll
            for (int q = 0; q < 8; ++q) {
                ulonglong2 bv = pb2[q];
                o[2 * q] = bv.x; o[2 * q + 1] = bv.y;
            }
            #pragma unroll
            for (int k = 0; k < 32; ++k) {
                unsigned long long rk = dup2(row[k]);
                const ulonglong2* w2 = (const ulonglong2*)(s.pwS + k * 32);
                #pragma unroll
                for (int q = 0; q < 8; ++q) {
                    ulonglong2 wv = w2[q];
                    ffma2(o[2 * q], rk, wv.x);
                    ffma2(o[2 * q + 1], rk, wv.y);
                }
            }
            #pragma unroll
            for (int q = 0; q < 16; ++q) {
                U64 u; u.u = o[q];
                s.pv[el][pr * NPVs + 2 * q]     = fast_tanh(u.f.x) + row[2 * q];
                s.pv[el][pr * NPVs + 2 * q + 1] = fast_tanh(u.f.y) + row[2 * q + 1];
            }
        }

        // (c) cm rank-1 GEMM with software-pipelined weight loads
        {
            const int kb2 = wid * 32;
            const int c0m = lane * 8;
            unsigned long long ca[2][4];
            #pragma unroll
            for (int el = 0; el < 2; ++el)
                #pragma unroll
                for (int p = 0; p < 4; ++p) ca[el][p] = 0ull;

            const float* wpc = WL + (256 + kb2) * 256 + c0m;
            ulonglong2 nA0 = *(const ulonglong2*)(wpc);
            ulonglong2 nB0 = *(const ulonglong2*)(wpc + 4);
            ulonglong2 nA1 = *(const ulonglong2*)(wpc + 256);
            ulonglong2 nB1 = *(const ulonglong2*)(wpc + 260);
            ulonglong2 nA2 = *(const ulonglong2*)(wpc + 512);
            ulonglong2 nB2 = *(const ulonglong2*)(wpc + 516);
            ulonglong2 nA3 = *(const ulonglong2*)(wpc + 768);
            ulonglong2 nB3 = *(const ulonglong2*)(wpc + 772);

            for (int kk = 0; kk < 32; kk += 4) {
                ulonglong2 wA0 = nA0, wB0 = nB0, wA1 = nA1, wB1 = nB1;
                ulonglong2 wA2 = nA2, wB2 = nB2, wA3 = nA3, wB3 = nB3;
                if (kk < 28) {
                    const float* wn = wpc + (kk + 4) * 256;
                    nA0 = *(const ulonglong2*)(wn);
                    nB0 = *(const ulonglong2*)(wn + 4);
                    nA1 = *(const ulonglong2*)(wn + 256);
                    nB1 = *(const ulonglong2*)(wn + 260);
                    nA2 = *(const ulonglong2*)(wn + 512);
                    nB2 = *(const ulonglong2*)(wn + 516);
                    nA3 = *(const ulonglong2*)(wn + 768);
                    nB3 = *(const ulonglong2*)(wn + 772);
                }
                #pragma unroll
                for (int el = 0; el < 2; ++el) {
                    float4 m4 = *(const float4*)&s.mumd[el][kb2 + kk];
                    unsigned long long d;
                    d = dup2(m4.x); ffma2(ca[el][0], d, wA0.x); ffma2(ca[el][1], d, wA0.y);
                                    ffma2(ca[el][2], d, wB0.x); ffma2(ca[el][3], d, wB0.y);
                    d = dup2(m4.y); ffma2(ca[el][0], d, wA1.x); ffma2(ca[el][1], d, wA1.y);
                                    ffma2(ca[el][2], d, wB1.x); ffma2(ca[el][3], d, wB1.y);
                    d = dup2(m4.z); ffma2(ca[el][0], d, wA2.x); ffma2(ca[el][1], d, wA2.y);
                                    ffma2(ca[el][2], d, wB2.x); ffma2(ca[el][3], d, wB2.y);
                    d = dup2(m4.w); ffma2(ca[el][0], d, wA3.x); ffma2(ca[el][1], d, wA3.y);
                                    ffma2(ca[el][2], d, wB3.x); ffma2(ca[el][3], d, wB3.y);
                }
            }
            #pragma unroll
            for (int el = 0; el < 2; ++el)
                #pragma unroll
                for (int p = 0; p < 4; ++p) {
                    U64 u; u.u = ca[el][p];
                    atomicAdd(&s.cm[el][swz(c0m + 2 * p)],     u.f.x);
                    atomicAdd(&s.cm[el][swz(c0m + 2 * p + 1)], u.f.y);
                }
        }

        // (d) main electron GEMM: warp (eh, ch, kh), pipelined weight prefetch
        {
            const int kh  = wid & 3;
            const int ch  = (wid >> 2) & 1;
            const int eh2 = wid >> 3;
            const int e0  = eh2 * 7;
            const int c0  = ch * 128 + lane * 4;
            unsigned long long acc[2][7][2];
            #pragma unroll
            for (int el = 0; el < 2; ++el)
                #pragma unroll
                for (int i = 0; i < 7; ++i) { acc[el][i][0] = 0ull; acc[el][i][1] = 0ull; }

            const int kb = kh * 64;
            const float* wpm = WL + kb * 256 + c0;
            ulonglong2 nw0 = *(const ulonglong2*)(wpm);
            ulonglong2 nw1 = *(const ulonglong2*)(wpm + 256);
            ulonglong2 nw2 = *(const ulonglong2*)(wpm + 512);
            ulonglong2 nw3 = *(const ulonglong2*)(wpm + 768);

            for (int kk = 0; kk < 64; kk += 4) {
                const int k = kb + kk;
                ulonglong2 w0 = nw0, w1 = nw1, w2 = nw2, w3 = nw3;
                if (kk < 60) {
                    const float* wn = wpm + (kk + 4) * 256;
                    nw0 = *(const ulonglong2*)(wn);
                    nw1 = *(const ulonglong2*)(wn + 256);
                    nw2 = *(const ulonglong2*)(wn + 512);
                    nw3 = *(const ulonglong2*)(wn + 768);
                }
                #pragma unroll
                for (int i = 0; i < 7; ++i) {
                    float4 a0 = *(const float4*)&s.sv[0][e0 + i][k];
                    float4 a1 = *(const float4*)&s.sv[1][e0 + i][k];
                    unsigned long long d;
                    d = dup2(a0.x); ffma2(acc[0][i][0], d, w0.x); ffma2(acc[0][i][1], d, w0.y);
                    d = dup2(a0.y); ffma2(acc[0][i][0], d, w1.x); ffma2(acc[0][i][1], d, w1.y);
                    d = dup2(a0.z); ffma2(acc[0][i][0], d, w2.x); ffma2(acc[0][i][1], d, w2.y);
                    d = dup2(a0.w); ffma2(acc[0][i][0], d, w3.x); ffma2(acc[0][i][1], d, w3.y);
                    d = dup2(a1.x); ffma2(acc[1][i][0], d, w0.x); ffma2(acc[1][i][1], d, w0.y);
                    d = dup2(a1.y); ffma2(acc[1][i][0], d, w1.x); ffma2(acc[1][i][1], d, w1.y);
                    d = dup2(a1.z); ffma2(acc[1][i][0], d, w2.x); ffma2(acc[1][i][1], d, w2.y);
                    d = dup2(a1.w); ffma2(acc[1][i][0], d, w3.x); ffma2(acc[1][i][1], d, w3.y);
                }
            }
            // pu/pd extension rows: kh handles k in [kh*8, kh*8+8)
            #pragma unroll
            for (int blk = 0; blk < 2; ++blk) {
                const int rowb = 768 + blk * 32;
                const int scrb = blk * 448;
                #pragma unroll
                for (int kk = 0; kk < 8; kk += 4) {
                    const int k = kh * 8 + kk;
                    const float* wp = WL + (rowb + k) * 256 + c0;
                    ulonglong2 w0 = *(const ulonglong2*)(wp);
                    ulonglong2 w1 = *(const ulonglong2*)(wp + 256);
                    ulonglong2 w2 = *(const ulonglong2*)(wp + 512);
                    ulonglong2 w3 = *(const ulonglong2*)(wp + 768);
                    #pragma unroll
                    for (int i = 0; i < 7; ++i) {
                        float4 a0 = *(const float4*)&s.scr[0][scrb + (e0 + i) * 32 + k];
                        float4 a1 = *(const float4*)&s.scr[1][scrb + (e0 + i) * 32 + k];
                        unsigned long long d;
                        d = dup2(a0.x); ffma2(acc[0][i][0], d, w0.x); ffma2(acc[0][i][1], d, w0.y);
                        d = dup2(a0.y); ffma2(acc[0][i][0], d, w1.x); ffma2(acc[0][i][1], d, w1.y);
                        d = dup2(a0.z); ffma2(acc[0][i][0], d, w2.x); ffma2(acc[0][i][1], d, w2.y);
                        d = dup2(a0.w); ffma2(acc[0][i][0], d, w3.x); ffma2(acc[0][i][1], d, w3.y);
                        d = dup2(a1.x); ffma2(acc[1][i][0], d, w0.x); ffma2(acc[1][i][1], d, w0.y);
                        d = dup2(a1.y); ffma2(acc[1][i][0], d, w1.x); ffma2(acc[1][i][1], d, w1.y);
                        d = dup2(a1.z); ffma2(acc[1][i][0], d, w2.x); ffma2(acc[1][i][1], d, w2.y);
                        d = dup2(a1.w); ffma2(acc[1][i][0], d, w3.x); ffma2(acc[1][i][1], d, w3.y);
                    }
                }
            }
            // plain conflict-free STS.128 of partials
            #pragma unroll
            for (int el = 0; el < 2; ++el)
                #pragma unroll
                for (int i = 0; i < 7; ++i) {
                    U64 u0; u0.u = acc[el][i][0];
                    U64 u1; u1.u = acc[el][i][1];
                    float4 v4 = make_float4(u0.f.x, u0.f.y, u1.f.x, u1.f.y);
                    *reinterpret_cast<float4*>(&s.red[kh][el][e0 + i][c0]) = v4;
                }
        }
        __syncthreads();

        // (e) epilogue: sum 4 k-slots + cm, tanh + residual
        {
            const float cmv = s.cm[tel][swz(tc)];
            #pragma unroll
            for (int e = 0; e < NE; ++e) {
                float v = cmv + s.red[0][tel][e][tc] + s.red[1][tel][e][tc]
                              + s.red[2][tel][e][tc] + s.red[3][tel][e][tc];
                v = fast_tanh(v);
                s.sv[tel][e][tc] = last ? v : (v + s.sv[tel][e][tc]);
            }
        }
        __syncthreads();
    }

    // ---------------- Orbitals (pipelined weight prefetch) ----------------
    for (int idx = t; idx < 2 * NE * NORB; idx += 512) {
        int el = idx / (NE * NORB), q = idx - el * (NE * NORB);
        int e = q / NORB, o = q - e * NORB;
        s.pv[el][e * NORB + swzo(o)] = (e < 7) ? wu_b[o] : wd_b[o];
    }
    __syncthreads();
    {
        const int kh  = wid & 3;
        const int eh2 = (wid >> 2) & 1;
        const int oel = wid >> 3;
        const int e0  = eh2 * 7;
        const int oc0 = lane * 4;
        if (oc0 < NORB) {
            const float* W = eh2 ? wd_w : wu_w;
            unsigned long long oa[7][2];
            #pragma unroll
            for (int i = 0; i < 7; ++i) { oa[i][0] = 0ull; oa[i][1] = 0ull; }
            const int kb = kh * 64;
            const float* wpo = W + kb * NORB + oc0;
            ulonglong2 nw0 = *(const ulonglong2*)(wpo);
            ulonglong2 nw1 = *(const ulonglong2*)(wpo + NORB);
            ulonglong2 nw2 = *(const ulonglong2*)(wpo + 2 * NORB);
            ulonglong2 nw3 = *(const ulonglong2*)(wpo + 3 * NORB);
            for (int kk = 0; kk < 64; kk += 4) {
                const int k = kb + kk;
                ulonglong2 w0 = nw0, w1 = nw1, w2 = nw2, w3 = nw3;
                if (kk < 60) {
                    const float* wn = wpo + (kk + 4) * NORB;
                    nw0 = *(const ulonglong2*)(wn);
                    nw1 = *(const ulonglong2*)(wn + NORB);
                    nw2 = *(const ulonglong2*)(wn + 2 * NORB);
                    nw3 = *(const ulonglong2*)(wn + 3 * NORB);
                }
                #pragma unroll
                for (int i = 0; i < 7; ++i) {
                    float4 a = *(const float4*)&s.sv[oel][e0 + i][k];
                    ffma2(oa[i][0], dup2(a.x), w0.x); ffma2(oa[i][1], dup2(a.x), w0.y);
                    ffma2(oa[i][0], dup2(a.y), w1.x); ffma2(oa[i][1], dup2(a.y), w1.y);
                    ffma2(oa[i][0], dup2(a.z), w2.x); ffma2(oa[i][1], dup2(a.z), w2.y);
                    ffma2(oa[i][0], dup2(a.w), w3.x); ffma2(oa[i][1], dup2(a.w), w3.y);
                }
            }
            #pragma unroll
            for (int i = 0; i < 7; ++i)
                #pragma unroll
                for (int p = 0; p < 2; ++p) {
                    U64 u; u.u = oa[i][p];
                    int o0 = oc0 + 2 * p;
                    atomicAdd(&s.pv[oel][(e0 + i) * NORB + swzo(o0)],     u.f.x);
                    atomicAdd(&s.pv[oel][(e0 + i) * NORB + swzo(o0 + 1)], u.f.y);
                }
        }
    }
    __syncthreads();
    for (int idx = t; idx < 2 * NE * NORB; idx += 512) {
        int el = idx / (NE * NORB), q = idx - el * (NE * NORB);
        int e = q / NORB;
        s.pv[el][q] *= s.env[el][e];
    }
    __syncthreads();

    // ---------------- 2 x 32 slogdets of 7x7 ----------------
    if (t < 64) {
        const int el = t >> 5, tt = t & 31;
        const int sp = tt >> 4, d = tt & 15;
        float m[7][7];
        #pragma unroll
        for (int j = 0; j < 7; ++j) {
            int og = swzo(j * 16 + d);
            #pragma unroll
            for (int i = 0; i < 7; ++i)
                m[j][i] = s.pv[el][(sp * 7 + i) * NORB + og];
        }
        float ld = 0.f, sg = 1.f;
        #pragma unroll
        for (int col = 0; col < 7; ++col) {
            #pragma unroll
            for (int rr = col + 1; rr < 7; ++rr) {
                if (fabsf(m[rr][col]) > fabsf(m[col][col])) {
                    sg = -sg;
                    #pragma unroll
                    for (int cc = 0; cc < 7; ++cc) {
                        float tmp = m[col][cc]; m[col][cc] = m[rr][cc]; m[rr][cc] = tmp;
                    }
                }
            }
            float piv = m[col][col];
            sg = (piv < 0.f) ? -sg : sg;
            ld += __logf(fabsf(piv));
            float inv = 1.f / piv;
            #pragma unroll
            for (int rr = col + 1; rr < 7; ++rr) {
                float f = m[rr][col] * inv;
                #pragma unroll
                for (int cc = col + 1; cc < 7; ++cc)
                    m[rr][cc] -= f * m[col][cc];
            }
        }
        s.ldet[el][tt] = ld;
        s.sgn[el][tt] = sg;
    }
    __syncthreads();

    if (t < 2 && (b0 + t) < nb) {
        const int el = t;
        float l[16], mx = -3.4e38f;
        #pragma unroll
        for (int d = 0; d < 16; ++d) {
            l[d] = s.ldet[el][d] + s.ldet[el][16 + d];
            mx = fmaxf(mx, l[d]);
        }
        float psi = 0.f;
        #pragma unroll
        for (int d = 0; d < 16; ++d)
            psi += s.sgn[el][d] * s.sgn[el][16 + d] * __expf(l[d] - mx) * wf_w[d];
        out[b0 + el] = __logf(fabsf(psi)) + mx;
    }
}

extern "C" void kernel_launch(void* const* d_in, const int* in_sizes, int n_in,
                              void* d_out, int out_size)
{
    const float* r    = (const float*)d_in[0];
    const float* s_w0 = (const float*)d_in[1];
    const float* s_b0 = (const float*)d_in[2];
    const float* s_w  = (const float*)d_in[3];
    const float* s_b  = (const float*)d_in[4];
    const float* p_w0 = (const float*)d_in[5];
    const float* p_b0 = (const float*)d_in[6];
    const float* p_w  = (const float*)d_in[7];
    const float* p_b  = (const float*)d_in[8];
    const float* va_w = (const float*)d_in[9];
    const float* va_b = (const float*)d_in[10];
    const float* wu_w = (const float*)d_in[11];
    const float* wu_b = (const float*)d_in[12];
    const float* wd_w = (const float*)d_in[13];
    const float* wd_b = (const float*)d_in[14];
    const float* wf_w = (const float*)d_in[15];

    const int nb  = in_sizes[0] / (14 * 3);
    const int nb2 = (nb + 1) / 2;
    const int smem = (int)sizeof(Smem);
    cudaFuncSetAttribute(ansatz_kernel, cudaFuncAttributeMaxDynamicSharedMemorySize, smem);
    ansatz_kernel<<<nb2, 512, smem>>>(r, s_w0, s_b0, s_w, s_b, p_w0, p_b0, p_w, p_b,
                                      va_w, va_b, wu_w, wu_b, wd_w, wd_b, wf_w,
                                      (float*)d_out, nb);
}

// round 9
// speedup vs baseline: 2.5100x; 1.0444x over previous
#include <cuda_runtime.h>
#include <math.h>

#define NE    14
#define NSV   256
#define NPVs  33
#define NPAIR 196
#define NORB  112
#define NFB   3

struct __align__(16) Smem {
    float sv[2][NE][NSV];        // 28672 B
    float pv[2][NPAIR * NPVs];   // 51744 B (reused as orbm swizzled)
    float red[4][2][NE][NSV];    // 114688 B k-split partials (plain stores); reused by orbitals
    float scr[2][896];
    float mumd[2][512];
    float cm[2][NSV];
    float pwS[1024];             // staged pair weights
    float pbS[32];
    float m0P[2][16];            // layer-0 geometry means (separate from mumd: race-free fusion)
    float sin8[2][NE][8];
    float env[2][NE];
    float rl[2][NE][3];
    float ldet[2][32];
    float sgn[2][32];
};

union U64 { unsigned long long u; float2 f; };

__device__ __forceinline__ void ffma2(unsigned long long &d, unsigned long long a, unsigned long long b) {
    asm("fma.rn.f32x2 %0, %1, %2, %0;" : "+l"(d) : "l"(a), "l"(b));
}
__device__ __forceinline__ unsigned long long dup2(float x) {
    unsigned long long r;
    asm("mov.b64 %0, {%1, %1};" : "=l"(r) : "f"(x));
    return r;
}
__device__ __forceinline__ int swz(int c)  { return c ^ (c >> 5); }
__device__ __forceinline__ int swzo(int o) { return o ^ (o >> 5); }

__device__ __forceinline__ float fast_tanh(float x) {
    float e = __expf(2.0f * x);
    return 1.0f - __fdividef(2.0f, e + 1.0f);
}

__global__ void __launch_bounds__(512, 1)
ansatz_kernel(const float* __restrict__ r,
              const float* __restrict__ s_w0, const float* __restrict__ s_b0,
              const float* __restrict__ s_w,  const float* __restrict__ s_b,
              const float* __restrict__ p_w0, const float* __restrict__ p_b0,
              const float* __restrict__ p_w,  const float* __restrict__ p_b,
              const float* __restrict__ va_w, const float* __restrict__ va_b,
              const float* __restrict__ wu_w, const float* __restrict__ wu_b,
              const float* __restrict__ wd_w, const float* __restrict__ wd_b,
              const float* __restrict__ wf_w,
              float* __restrict__ out, int nb)
{
    extern __shared__ char smem_raw[];
    Smem& s = *reinterpret_cast<Smem*>(smem_raw);

    const int t    = threadIdx.x;
    const int lane = t & 31;
    const int wid  = t >> 5;
    const int b0   = blockIdx.x * 2;
    const float inv7 = 1.0f / 7.0f;

    const int tel = t >> 8;
    const int tc  = t & 255;

    // ---------------- Phase 0: geometry ----------------
    for (int q = t; q < 2 * NE * 3; q += 512) {
        int el = q / (NE * 3);
        int bel = b0 + el; if (bel >= nb) bel = nb - 1;
        ((float*)s.rl[el])[q - el * (NE * 3)] = r[bel * (NE * 3) + (q - el * (NE * 3))];
    }
    __syncthreads();

    if (t < 2 * NE) {
        int el = t / NE, e = t - el * NE;
        float x = s.rl[el][e][0], y = s.rl[el][e][1], z = s.rl[el][e][2];
        float ev = 0.f;
        #pragma unroll
        for (int a = 0; a < 2; ++a) {
            float dz = z - (a ? 1.4f : 0.0f);
            float len = sqrtf(x * x + y * y + dz * dz);
            s.sin8[el][e][a * 4 + 0] = x;
            s.sin8[el][e][a * 4 + 1] = y;
            s.sin8[el][e][a * 4 + 2] = dz;
            s.sin8[el][e][a * 4 + 3] = len;
            ev += __expf(-len);
        }
        s.env[el][e] = ev;
    }
    if (t < 2 * NPAIR) {
        int el = t / NPAIR, pr = t - el * NPAIR;
        int i = pr / 14, j = pr - i * 14;
        float dx = s.rl[el][j][0] - s.rl[el][i][0];
        float dy = s.rl[el][j][1] - s.rl[el][i][1];
        float dz = s.rl[el][j][2] - s.rl[el][i][2];
        float ax = dx, ay = dy, az = dz;
        if (i == j) { ax += 1.f; ay += 1.f; az += 1.f; }
        float len = sqrtf(ax * ax + ay * ay + az * az);
        s.scr[el][pr * 4 + 0] = dx; s.scr[el][pr * 4 + 1] = dy;
        s.scr[el][pr * 4 + 2] = dz; s.scr[el][pr * 4 + 3] = len;
    }
    __syncthreads();

    // layer-0 geometry means (into m0P, NOT mumd — fusion writes mumd later)
    if (t < 32) {
        int el = t >> 4, q = t & 15;
        int k = q & 7, half = q >> 3;
        float su = 0.f;
        #pragma unroll
        for (int e = 0; e < 7; ++e) su += s.sin8[el][half * 7 + e][k];
        s.m0P[el][half * 8 + k] = su * inv7;
    }
    if (t >= 64 && t < 64 + 224) {
        int q2 = t - 64;
        int el = q2 / 112, q = q2 - el * 112;
        int dn = (q >= 56) ? 1 : 0;
        int qq = q - dn * 56;
        int e = qq >> 2, k = qq & 3;
        int i0 = dn ? 7 : 0;
        float su = 0.f;
        #pragma unroll
        for (int ii = 0; ii < 7; ++ii) su += s.scr[el][((i0 + ii) * 14 + e) * 4 + k];
        s.scr[el][784 + dn * 56 + e * 4 + k] = su * inv7;
    }
    __syncthreads();

    // ---------------- Layer 0 (fused epilogue: sv + mumd + cm init) ----------------
    {
        float pnew[32];
        const bool prow = (t < 2 * NPAIR);
        int pel = 0, pr = 0;
        if (prow) {
            pel = t / NPAIR; pr = t - pel * NPAIR;
            const float* pin = s.scr[pel] + pr * 4;
            float r0 = pin[0], r1 = pin[1], r2 = pin[2], r3 = pin[3];
            #pragma unroll
            for (int c2 = 0; c2 < 32; ++c2) {
                float v = p_b0[c2]
                        + r0 * p_w0[0 * 32 + c2] + r1 * p_w0[1 * 32 + c2]
                        + r2 * p_w0[2 * 32 + c2] + r3 * p_w0[3 * 32 + c2];
                pnew[c2] = fast_tanh(v);
            }
        }
        float cm0 = s_b0[tc];
        #pragma unroll
        for (int k = 0; k < 8; ++k)
            cm0 += s.m0P[tel][k] * s_w0[(8 + k) * 256 + tc] + s.m0P[tel][8 + k] * s_w0[(16 + k) * 256 + tc];
        float acc[NE];
        #pragma unroll
        for (int e = 0; e < NE; ++e) acc[e] = cm0;
        #pragma unroll
        for (int k = 0; k < 8; ++k) {
            float w = s_w0[k * 256 + tc];
            #pragma unroll
            for (int e = 0; e < NE; ++e) acc[e] += s.sin8[tel][e][k] * w;
        }
        const float* pu0 = s.scr[tel] + 784;
        const float* pd0 = s.scr[tel] + 840;
        #pragma unroll
        for (int k = 0; k < 4; ++k) {
            float wuv = s_w0[(24 + k) * 256 + tc];
            float wdv = s_w0[(28 + k) * 256 + tc];
            #pragma unroll
            for (int e = 0; e < NE; ++e)
                acc[e] += pu0[e * 4 + k] * wuv + pd0[e * 4 + k] * wdv;
        }
        // fused: write sv + compute mu/md + cm bias init for FB layer 0
        float su = 0.f, sd = 0.f;
        #pragma unroll
        for (int e = 0; e < NE; ++e) {
            float v = fast_tanh(acc[e]);
            s.sv[tel][e][tc] = v;
            if (e < 7) su += v; else sd += v;
        }
        s.mumd[tel][tc]       = su * inv7;
        s.mumd[tel][256 + tc] = sd * inv7;
        s.cm[tel][swz(tc)]    = s_b[tc];
        if (prow) {
            #pragma unroll
            for (int c2 = 0; c2 < 32; ++c2) s.pv[pel][pr * NPVs + c2] = pnew[c2];
        }
    }
    __syncthreads();

    // ---------------- prep for il=0: scr pair-means + pwS staging ----------------
    for (int idx = t; idx < 2 * 896; idx += 512) {
        int el = idx / 896, q2 = idx - el * 896;
        int dn = (q2 >= 448) ? 1 : 0;
        int q = q2 - dn * 448;
        int e = q >> 5, k = q & 31;
        int i0 = dn ? 7 : 0;
        float su = 0.f;
        #pragma unroll
        for (int ii = 0; ii < 7; ++ii) su += s.pv[el][((i0 + ii) * 14 + e) * NPVs + k];
        s.scr[el][q2] = su * inv7;
    }
    #pragma unroll
    for (int idx = t; idx < 1024; idx += 512) s.pwS[idx] = p_w[idx];
    if (t < 32) s.pbS[t] = p_b[t];
    __syncthreads();

    // ---------------- FB layers + final va ----------------
    for (int il = 0; il <= NFB; ++il) {
        const bool last = (il == NFB);
        const float* WL = last ? va_w : (s_w + il * (832 * 256));

        // (b) pair GEMM — weights from shared
        if (!last && t < 2 * NPAIR) {
            int el = t / NPAIR, pr = t - el * NPAIR;
            float row[32];
            #pragma unroll
            for (int k = 0; k < 32; ++k) row[k] = s.pv[el][pr * NPVs + k];
            unsigned long long o[16];
            const ulonglong2* pb2 = (const ulonglong2*)s.pbS;
            #pragma unroll
            for (int q = 0; q < 8; ++q) {
                ulonglong2 bv = pb2[q];
                o[2 * q] = bv.x; o[2 * q + 1] = bv.y;
            }
            #pragma unroll
            for (int k = 0; k < 32; ++k) {
                unsigned long long rk = dup2(row[k]);
                const ulonglong2* w2 = (const ulonglong2*)(s.pwS + k * 32);
                #pragma unroll
                for (int q = 0; q < 8; ++q) {
                    ulonglong2 wv = w2[q];
                    ffma2(o[2 * q], rk, wv.x);
                    ffma2(o[2 * q + 1], rk, wv.y);
                }
            }
            #pragma unroll
            for (int q = 0; q < 16; ++q) {
                U64 u; u.u = o[q];
                s.pv[el][pr * NPVs + 2 * q]     = fast_tanh(u.f.x) + row[2 * q];
                s.pv[el][pr * NPVs + 2 * q + 1] = fast_tanh(u.f.y) + row[2 * q + 1];
            }
        }

        // (c) cm rank-1 GEMM, pipelined (guard-free prefetch: rows stay < 832)
        {
            const int kb2 = wid * 32;
            const int c0m = lane * 8;
            unsigned long long ca[2][4];
            #pragma unroll
            for (int el = 0; el < 2; ++el)
                #pragma unroll
                for (int p = 0; p < 4; ++p) ca[el][p] = 0ull;

            const float* wpc = WL + (256 + kb2) * 256 + c0m;
            ulonglong2 nA0 = *(const ulonglong2*)(wpc);
            ulonglong2 nB0 = *(const ulonglong2*)(wpc + 4);
            ulonglong2 nA1 = *(const ulonglong2*)(wpc + 256);
            ulonglong2 nB1 = *(const ulonglong2*)(wpc + 260);
            ulonglong2 nA2 = *(const ulonglong2*)(wpc + 512);
            ulonglong2 nB2 = *(const ulonglong2*)(wpc + 516);
            ulonglong2 nA3 = *(const ulonglong2*)(wpc + 768);
            ulonglong2 nB3 = *(const ulonglong2*)(wpc + 772);

            for (int kk = 0; kk < 32; kk += 4) {
                ulonglong2 wA0 = nA0, wB0 = nB0, wA1 = nA1, wB1 = nB1;
                ulonglong2 wA2 = nA2, wB2 = nB2, wA3 = nA3, wB3 = nB3;
                const float* wn = wpc + (kk + 4) * 256;   // row <= 256+kb2+35 <= 771 < 832
                nA0 = *(const ulonglong2*)(wn);
                nB0 = *(const ulonglong2*)(wn + 4);
                nA1 = *(const ulonglong2*)(wn + 256);
                nB1 = *(const ulonglong2*)(wn + 260);
                nA2 = *(const ulonglong2*)(wn + 512);
                nB2 = *(const ulonglong2*)(wn + 516);
                nA3 = *(const ulonglong2*)(wn + 768);
                nB3 = *(const ulonglong2*)(wn + 772);
                #pragma unroll
                for (int el = 0; el < 2; ++el) {
                    float4 m4 = *(const float4*)&s.mumd[el][kb2 + kk];
                    unsigned long long d;
                    d = dup2(m4.x); ffma2(ca[el][0], d, wA0.x); ffma2(ca[el][1], d, wA0.y);
                                    ffma2(ca[el][2], d, wB0.x); ffma2(ca[el][3], d, wB0.y);
                    d = dup2(m4.y); ffma2(ca[el][0], d, wA1.x); ffma2(ca[el][1], d, wA1.y);
                                    ffma2(ca[el][2], d, wB1.x); ffma2(ca[el][3], d, wB1.y);
                    d = dup2(m4.z); ffma2(ca[el][0], d, wA2.x); ffma2(ca[el][1], d, wA2.y);
                                    ffma2(ca[el][2], d, wB2.x); ffma2(ca[el][3], d, wB2.y);
                    d = dup2(m4.w); ffma2(ca[el][0], d, wA3.x); ffma2(ca[el][1], d, wA3.y);
                                    ffma2(ca[el][2], d, wB3.x); ffma2(ca[el][3], d, wB3.y);
                }
            }
            #pragma unroll
            for (int el = 0; el < 2; ++el)
                #pragma unroll
                for (int p = 0; p < 4; ++p) {
                    U64 u; u.u = ca[el][p];
                    atomicAdd(&s.cm[el][swz(c0m + 2 * p)],     u.f.x);
                    atomicAdd(&s.cm[el][swz(c0m + 2 * p + 1)], u.f.y);
                }
        }

        // (d) main electron GEMM: warp (eh, ch, kh), pipelined, guard-free prefetch
        {
            const int kh  = wid & 3;
            const int ch  = (wid >> 2) & 1;
            const int eh2 = wid >> 3;
            const int e0  = eh2 * 7;
            const int c0  = ch * 128 + lane * 4;
            unsigned long long acc[2][7][2];
            #pragma unroll
            for (int el = 0; el < 2; ++el)
                #pragma unroll
                for (int i = 0; i < 7; ++i) { acc[el][i][0] = 0ull; acc[el][i][1] = 0ull; }

            const int kb = kh * 64;
            const float* wpm = WL + kb * 256 + c0;
            ulonglong2 nw0 = *(const ulonglong2*)(wpm);
            ulonglong2 nw1 = *(const ulonglong2*)(wpm + 256);
            ulonglong2 nw2 = *(const ulonglong2*)(wpm + 512);
            ulonglong2 nw3 = *(const ulonglong2*)(wpm + 768);

            for (int kk = 0; kk < 64; kk += 4) {
                const int k = kb + kk;
                ulonglong2 w0 = nw0, w1 = nw1, w2 = nw2, w3 = nw3;
                const float* wn = wpm + (kk + 4) * 256;   // row <= kb+67 <= 259 < 832
                nw0 = *(const ulonglong2*)(wn);
                nw1 = *(const ulonglong2*)(wn + 256);
                nw2 = *(const ulonglong2*)(wn + 512);
                nw3 = *(const ulonglong2*)(wn + 768);
                #pragma unroll
                for (int i = 0; i < 7; ++i) {
                    float4 a0 = *(const float4*)&s.sv[0][e0 + i][k];
                    float4 a1 = *(const float4*)&s.sv[1][e0 + i][k];
                    unsigned long long d;
                    d = dup2(a0.x); ffma2(acc[0][i][0], d, w0.x); ffma2(acc[0][i][1], d, w0.y);
                    d = dup2(a0.y); ffma2(acc[0][i][0], d, w1.x); ffma2(acc[0][i][1], d, w1.y);
                    d = dup2(a0.z); ffma2(acc[0][i][0], d, w2.x); ffma2(acc[0][i][1], d, w2.y);
                    d = dup2(a0.w); ffma2(acc[0][i][0], d, w3.x); ffma2(acc[0][i][1], d, w3.y);
                    d = dup2(a1.x); ffma2(acc[1][i][0], d, w0.x); ffma2(acc[1][i][1], d, w0.y);
                    d = dup2(a1.y); ffma2(acc[1][i][0], d, w1.x); ffma2(acc[1][i][1], d, w1.y);
                    d = dup2(a1.z); ffma2(acc[1][i][0], d, w2.x); ffma2(acc[1][i][1], d, w2.y);
                    d = dup2(a1.w); ffma2(acc[1][i][0], d, w3.x); ffma2(acc[1][i][1], d, w3.y);
                }
            }
            // pu/pd extension rows: kh handles k in [kh*8, kh*8+8)
            #pragma unroll
            for (int blk = 0; blk < 2; ++blk) {
                const int rowb = 768 + blk * 32;
                const int scrb = blk * 448;
                #pragma unroll
                for (int kk = 0; kk < 8; kk += 4) {
                    const int k = kh * 8 + kk;
                    const float* wp = WL + (rowb + k) * 256 + c0;
                    ulonglong2 w0 = *(const ulonglong2*)(wp);
                    ulonglong2 w1 = *(const ulonglong2*)(wp + 256);
                    ulonglong2 w2 = *(const ulonglong2*)(wp + 512);
                    ulonglong2 w3 = *(const ulonglong2*)(wp + 768);
                    #pragma unroll
                    for (int i = 0; i < 7; ++i) {
                        float4 a0 = *(const float4*)&s.scr[0][scrb + (e0 + i) * 32 + k];
                        float4 a1 = *(const float4*)&s.scr[1][scrb + (e0 + i) * 32 + k];
                        unsigned long long d;
                        d = dup2(a0.x); ffma2(acc[0][i][0], d, w0.x); ffma2(acc[0][i][1], d, w0.y);
                        d = dup2(a0.y); ffma2(acc[0][i][0], d, w1.x); ffma2(acc[0][i][1], d, w1.y);
                        d = dup2(a0.z); ffma2(acc[0][i][0], d, w2.x); ffma2(acc[0][i][1], d, w2.y);
                        d = dup2(a0.w); ffma2(acc[0][i][0], d, w3.x); ffma2(acc[0][i][1], d, w3.y);
                        d = dup2(a1.x); ffma2(acc[1][i][0], d, w0.x); ffma2(acc[1][i][1], d, w0.y);
                        d = dup2(a1.y); ffma2(acc[1][i][0], d, w1.x); ffma2(acc[1][i][1], d, w1.y);
                        d = dup2(a1.z); ffma2(acc[1][i][0], d, w2.x); ffma2(acc[1][i][1], d, w2.y);
                        d = dup2(a1.w); ffma2(acc[1][i][0], d, w3.x); ffma2(acc[1][i][1], d, w3.y);
                    }
                }
            }
            // plain conflict-free STS.128 of partials
            #pragma unroll
            for (int el = 0; el < 2; ++el)
                #pragma unroll
                for (int i = 0; i < 7; ++i) {
                    U64 u0; u0.u = acc[el][i][0];
                    U64 u1; u1.u = acc[el][i][1];
                    float4 v4 = make_float4(u0.f.x, u0.f.y, u1.f.x, u1.f.y);
                    *reinterpret_cast<float4*>(&s.red[kh][el][e0 + i][c0]) = v4;
                }
        }
        __syncthreads();

        // (E) fused: epilogue + next-layer means/cm-init/scr/pwS
        {
            const int cs = swz(tc);
            const float cmv = s.cm[tel][cs];
            float su = 0.f, sd = 0.f;
            #pragma unroll
            for (int e = 0; e < NE; ++e) {
                float v = cmv + s.red[0][tel][e][tc] + s.red[1][tel][e][tc]
                              + s.red[2][tel][e][tc] + s.red[3][tel][e][tc];
                v = fast_tanh(v);
                if (!last) v += s.sv[tel][e][tc];
                s.sv[tel][e][tc] = v;
                if (e < 7) su += v; else sd += v;
            }
            if (!last) {
                s.mumd[tel][tc]       = su * inv7;
                s.mumd[tel][256 + tc] = sd * inv7;
                const float* bN = (il == NFB - 1) ? va_b : (s_b + (il + 1) * 256);
                s.cm[tel][cs] = bN[tc];
            }
        }
        if (!last) {
            for (int idx = t; idx < 2 * 896; idx += 512) {
                int el = idx / 896, q2 = idx - el * 896;
                int dn = (q2 >= 448) ? 1 : 0;
                int q = q2 - dn * 448;
                int e = q >> 5, k = q & 31;
                int i0 = dn ? 7 : 0;
                float su = 0.f;
                #pragma unroll
                for (int ii = 0; ii < 7; ++ii) su += s.pv[el][((i0 + ii) * 14 + e) * NPVs + k];
                s.scr[el][q2] = su * inv7;
            }
            if (il + 1 < NFB) {
                #pragma unroll
                for (int idx = t; idx < 1024; idx += 512) s.pwS[idx] = p_w[(il + 1) * 1024 + idx];
                if (t < 32) s.pbS[t] = p_b[(il + 1) * 32 + t];
            }
        }
        __syncthreads();
    }

    // ---------------- Orbitals: partials to red (no atomics), then reduce ----------------
    {
        const int kh  = wid & 3;
        const int eh2 = (wid >> 2) & 1;
        const int oel = wid >> 3;
        const int e0  = eh2 * 7;
        const int oc0 = lane * 4;
        if (oc0 < NORB) {
            const float* W = eh2 ? wd_w : wu_w;
            unsigned long long oa[7][2];
            #pragma unroll
            for (int i = 0; i < 7; ++i) { oa[i][0] = 0ull; oa[i][1] = 0ull; }
            const int kb = kh * 64;
            const float* wpo = W + kb * NORB + oc0;
            ulonglong2 nw0 = *(const ulonglong2*)(wpo);
            ulonglong2 nw1 = *(const ulonglong2*)(wpo + NORB);
            ulonglong2 nw2 = *(const ulonglong2*)(wpo + 2 * NORB);
            ulonglong2 nw3 = *(const ulonglong2*)(wpo + 3 * NORB);
            for (int kk = 0; kk < 64; kk += 4) {
                const int k = kb + kk;
                ulonglong2 w0 = nw0, w1 = nw1, w2 = nw2, w3 = nw3;
                if (kk < 60) {
                    const float* wn = wpo + (kk + 4) * NORB;
                    nw0 = *(const ulonglong2*)(wn);
                    nw1 = *(const ulonglong2*)(wn + NORB);
                    nw2 = *(const ulonglong2*)(wn + 2 * NORB);
                    nw3 = *(const ulonglong2*)(wn + 3 * NORB);
                }
                #pragma unroll
                for (int i = 0; i < 7; ++i) {
                    float4 a = *(const float4*)&s.sv[oel][e0 + i][k];
                    ffma2(oa[i][0], dup2(a.x), w0.x); ffma2(oa[i][1], dup2(a.x), w0.y);
                    ffma2(oa[i][0], dup2(a.y), w1.x); ffma2(oa[i][1], dup2(a.y), w1.y);
                    ffma2(oa[i][0], dup2(a.z), w2.x); ffma2(oa[i][1], dup2(a.z), w2.y);
                    ffma2(oa[i][0], dup2(a.w), w3.x); ffma2(oa[i][1], dup2(a.w), w3.y);
                }
            }
            #pragma unroll
            for (int i = 0; i < 7; ++i) {
                U64 u0; u0.u = oa[i][0];
                U64 u1; u1.u = oa[i][1];
                float4 v4 = make_float4(u0.f.x, u0.f.y, u1.f.x, u1.f.y);
                *reinterpret_cast<float4*>(&s.red[kh][oel][e0 + i][oc0]) = v4;
            }
        }
    }
    __syncthreads();
    // reduce partials: bias + sum over kh, × env, write orbm (swizzled) into pv region
    for (int idx = t; idx < 2 * NE * NORB; idx += 512) {
        int oel = idx / (NE * NORB), q = idx - oel * (NE * NORB);
        int e = q / NORB, o = q - e * NORB;
        float v = ((e < 7) ? wu_b[o] : wd_b[o])
                + s.red[0][oel][e][o] + s.red[1][oel][e][o]
                + s.red[2][oel][e][o] + s.red[3][oel][e][o];
        s.pv[oel][e * NORB + swzo(o)] = v * s.env[oel][e];
    }
    __syncthreads();

    // ---------------- 2 x 32 slogdets of 7x7 ----------------
    if (t < 64) {
        const int el = t >> 5, tt = t & 31;
        const int sp = tt >> 4, d = tt & 15;
        float m[7][7];
        #pragma unroll
        for (int j = 0; j < 7; ++j) {
            int og = swzo(j * 16 + d);
            #pragma unroll
            for (int i = 0; i < 7; ++i)
                m[j][i] = s.pv[el][(sp * 7 + i) * NORB + og];
        }
        float ld = 0.f, sg = 1.f;
        #pragma unroll
        for (int col = 0; col < 7; ++col) {
            #pragma unroll
            for (int rr = col + 1; rr < 7; ++rr) {
                if (fabsf(m[rr][col]) > fabsf(m[col][col])) {
                    sg = -sg;
                    #pragma unroll
                    for (int cc = 0; cc < 7; ++cc) {
                        float tmp = m[col][cc]; m[col][cc] = m[rr][cc]; m[rr][cc] = tmp;
                    }
                }
            }
            float piv = m[col][col];
            sg = (piv < 0.f) ? -sg : sg;
            ld += __logf(fabsf(piv));
            float inv = 1.f / piv;
            #pragma unroll
            for (int rr = col + 1; rr < 7; ++rr) {
                float f = m[rr][col] * inv;
                #pragma unroll
                for (int cc = col + 1; cc < 7; ++cc)
                    m[rr][cc] -= f * m[col][cc];
            }
        }
        s.ldet[el][tt] = ld;
        s.sgn[el][tt] = sg;
    }
    __syncthreads();

    if (t < 2 && (b0 + t) < nb) {
        const int el = t;
        float l[16], mx = -3.4e38f;
        #pragma unroll
        for (int d = 0; d < 16; ++d) {
            l[d] = s.ldet[el][d] + s.ldet[el][16 + d];
            mx = fmaxf(mx, l[d]);
        }
        float psi = 0.f;
        #pragma unroll
        for (int d = 0; d < 16; ++d)
            psi += s.sgn[el][d] * s.sgn[el][16 + d] * __expf(l[d] - mx) * wf_w[d];
        out[b0 + el] = __logf(fabsf(psi)) + mx;
    }
}

extern "C" void kernel_launch(void* const* d_in, const int* in_sizes, int n_in,
                              void* d_out, int out_size)
{
    const float* r    = (const float*)d_in[0];
    const float* s_w0 = (const float*)d_in[1];
    const float* s_b0 = (const float*)d_in[2];
    const float* s_w  = (const float*)d_in[3];
    const float* s_b  = (const float*)d_in[4];
    const float* p_w0 = (const float*)d_in[5];
    const float* p_b0 = (const float*)d_in[6];
    const float* p_w  = (const float*)d_in[7];
    const float* p_b  = (const float*)d_in[8];
    const float* va_w = (const float*)d_in[9];
    const float* va_b = (const float*)d_in[10];
    const float* wu_w = (const float*)d_in[11];
    const float* wu_b = (const float*)d_in[12];
    const float* wd_w = (const float*)d_in[13];
    const float* wd_b = (const float*)d_in[14];
    const float* wf_w = (const float*)d_in[15];

    const int nb  = in_sizes[0] / (14 * 3);
    const int nb2 = (nb + 1) / 2;
    const int smem = (int)sizeof(Smem);
    cudaFuncSetAttribute(ansatz_kernel, cudaFuncAttributeMaxDynamicSharedMemorySize, smem);
    ansatz_kernel<<<nb2, 512, smem>>>(r, s_w0, s_b0, s_w, s_b, p_w0, p_b0, p_w, p_b,
                                      va_w, va_b, wu_w, wu_b, wd_w, wd_b, wf_w,
                                      (float*)d_out, nb);
}